// round 3
// baseline (speedup 1.0000x reference)
#include <cuda_runtime.h>

#define N_NODES 50000
#define N_EDGES 50000
#define NNZ     800000
#define IN_C    256
#define HID_C   128
#define OUT_C   64

// ---------------- scratch (device globals; referenced by name only) ----------------
__device__ float g_xw [N_NODES * HID_C];   // X@W1 ; reused as f1@W2 (N x 64)
__device__ float g_m  [N_EDGES * HID_C];   // per-edge accumulator
__device__ float g_acc[N_NODES * HID_C];   // per-node accumulator
__device__ float g_deg[N_NODES];
__device__ float g_be [N_EDGES];
__device__ int   g_is64;                   // 1 if hyperedge_index is int64, 0 if int32

// ---------------- index dtype detection ----------------
// int64 indices: every 8-byte word < N_EDGES. int32 data read as int64: value
// = lo + hi*2^32 with hi a random index in [0,50000) -> almost surely huge.
__global__ void detect_dtype_kernel(const void* he) {
    __shared__ int bad;
    if (threadIdx.x == 0) bad = 0;
    __syncthreads();
    const long long* p = (const long long*)he;
    long long v = p[threadIdx.x + blockDim.x * blockIdx.x];
    if (v < 0 || v >= (long long)N_EDGES) atomicOr(&bad, 1);
    __syncthreads();
    if (threadIdx.x == 0 && bad) atomicExch(&g_is64, 0);
}

__global__ void init_flag_kernel() { g_is64 = 1; }

__device__ __forceinline__ int idx_node(const void* he, int i) {
    if (g_is64) return (int)((const long long*)he)[i];
    return ((const int*)he)[i];
}
__device__ __forceinline__ int idx_edge(const void* he, int i) {
    if (g_is64) return (int)((const long long*)he)[NNZ + i];
    return ((const int*)he)[NNZ + i];
}

// ---------------- zero / degree ----------------
__global__ void zero_deg_kernel() {
    int i = blockIdx.x * blockDim.x + threadIdx.x;
    if (i < N_NODES) g_deg[i] = 0.0f;
    if (i < N_EDGES) g_be[i]  = 0.0f;
}

template<int F>
__global__ void zero_m_kernel() {
    int i = blockIdx.x * blockDim.x + threadIdx.x;
    if (i < N_EDGES * F) g_m[i] = 0.0f;
}

template<int F>
__global__ void zero_acc_kernel() {
    int i = blockIdx.x * blockDim.x + threadIdx.x;
    if (i < N_NODES * F) g_acc[i] = 0.0f;
}

__global__ void deg_kernel(const void* __restrict__ he) {
    int i = blockIdx.x * blockDim.x + threadIdx.x;
    if (i < NNZ) {
        int n = idx_node(he, i);
        int e = idx_edge(he, i);
        if (n >= 0 && n < N_NODES) atomicAdd(&g_deg[n], 1.0f);
        if (e >= 0 && e < N_EDGES) atomicAdd(&g_be[e],  1.0f);
    }
}

// ---------------- scatter: node -> edge (src = g_xw, dst = g_m) ----------------
template<int F>
__global__ void scatter_ne(const void* __restrict__ he) {
    constexpr int C4 = F / 4;
    int t = blockIdx.x * blockDim.x + threadIdx.x;
    if (t >= NNZ * C4) return;
    int e = t / C4;
    int c = (t % C4) * 4;
    int n  = idx_node(he, e);
    int ed = idx_edge(he, e);
    if ((unsigned)n >= N_NODES || (unsigned)ed >= N_EDGES) return;
    float4 v = *reinterpret_cast<const float4*>(&g_xw[(size_t)n * F + c]);
    float* dst = &g_m[(size_t)ed * F + c];
    atomicAdd(dst + 0, v.x);
    atomicAdd(dst + 1, v.y);
    atomicAdd(dst + 2, v.z);
    atomicAdd(dst + 3, v.w);
}

// ---------------- scatter: edge -> node with Binv fused (src = g_m, dst = g_acc) ----
template<int F>
__global__ void scatter_en(const void* __restrict__ he) {
    constexpr int C4 = F / 4;
    int t = blockIdx.x * blockDim.x + threadIdx.x;
    if (t >= NNZ * C4) return;
    int e = t / C4;
    int c = (t % C4) * 4;
    int n  = idx_node(he, e);
    int ed = idx_edge(he, e);
    if ((unsigned)n >= N_NODES || (unsigned)ed >= N_EDGES) return;
    float bv = g_be[ed];
    float s  = (bv > 0.0f) ? (1.0f / bv) : 0.0f;
    float4 v = *reinterpret_cast<const float4*>(&g_m[(size_t)ed * F + c]);
    float* dst = &g_acc[(size_t)n * F + c];
    atomicAdd(dst + 0, v.x * s);
    atomicAdd(dst + 1, v.y * s);
    atomicAdd(dst + 2, v.z * s);
    atomicAdd(dst + 3, v.w * s);
}

// ---------------- finalize: out = relu(g_acc * Dinv + bias) ----------------
template<int F>
__global__ void finalize_kernel(const float* __restrict__ bias,
                                float* __restrict__ out) {
    int t = blockIdx.x * blockDim.x + threadIdx.x;
    if (t >= N_NODES * F) return;
    int row = t / F, c = t % F;
    float d = g_deg[row];
    float dinv = (d > 0.0f) ? (1.0f / d) : 0.0f;
    float v = fmaf(g_acc[t], dinv, bias[c]);
    out[t] = fmaxf(v, 0.0f);
}

// ---------------- register-tiled SGEMM: C[M,N] = A[M,K] @ B[K,N] (+bias) ----------
template<int K, int N, bool TO_XW>
__global__ void gemm_kernel(const float* __restrict__ A, const float* __restrict__ B,
                            const float* __restrict__ bias, float* __restrict__ C, int M) {
    constexpr int BM = 64, BK = 32;
    constexpr int TM = 4;
    constexpr int TN = N / 16;            // 8 for N=128, 4 for N=64
    __shared__ float As[BK][BM + 4];
    __shared__ float Bs[BK][N];

    const int tid = threadIdx.x;          // 256 threads
    const int tx = tid & 15;
    const int ty = tid >> 4;
    const int blockRow = blockIdx.x * BM;

    float* Cp = TO_XW ? g_xw : C;

    float acc[TM][TN];
    #pragma unroll
    for (int i = 0; i < TM; i++)
        #pragma unroll
        for (int j = 0; j < TN; j++) acc[i][j] = 0.0f;

    for (int k0 = 0; k0 < K; k0 += BK) {
        #pragma unroll
        for (int l = 0; l < 2; l++) {
            int idx = tid + l * 256;
            int r = idx >> 3;
            int c = (idx & 7) * 4;
            int grow = blockRow + r;
            float4 v = make_float4(0.f, 0.f, 0.f, 0.f);
            if (grow < M)
                v = *reinterpret_cast<const float4*>(A + (size_t)grow * K + k0 + c);
            As[c + 0][r] = v.x; As[c + 1][r] = v.y;
            As[c + 2][r] = v.z; As[c + 3][r] = v.w;
        }
        constexpr int BF4 = BK * N / 4;
        #pragma unroll
        for (int l = 0; l < BF4 / 256; l++) {
            int idx = tid + l * 256;
            int r = idx / (N / 4);
            int c = (idx % (N / 4)) * 4;
            *reinterpret_cast<float4*>(&Bs[r][c]) =
                *reinterpret_cast<const float4*>(B + (size_t)(k0 + r) * N + c);
        }
        __syncthreads();

        #pragma unroll
        for (int k = 0; k < BK; k++) {
            float a[TM], b[TN];
            #pragma unroll
            for (int i = 0; i < TM; i++) a[i] = As[k][i * 16 + ty];
            #pragma unroll
            for (int j = 0; j < TN; j++) b[j] = Bs[k][tx * TN + j];
            #pragma unroll
            for (int i = 0; i < TM; i++)
                #pragma unroll
                for (int j = 0; j < TN; j++)
                    acc[i][j] = fmaf(a[i], b[j], acc[i][j]);
        }
        __syncthreads();
    }

    #pragma unroll
    for (int i = 0; i < TM; i++) {
        int row = blockRow + i * 16 + ty;
        if (row >= M) continue;
        #pragma unroll
        for (int j = 0; j < TN; j += 4) {
            int col = tx * TN + j;
            float4 v;
            v.x = acc[i][j + 0]; v.y = acc[i][j + 1];
            v.z = acc[i][j + 2]; v.w = acc[i][j + 3];
            if (bias) {
                v.x += bias[col + 0]; v.y += bias[col + 1];
                v.z += bias[col + 2]; v.w += bias[col + 3];
            }
            *reinterpret_cast<float4*>(Cp + (size_t)row * N + col) = v;
        }
    }
}

// ---------------- launch ----------------
extern "C" void kernel_launch(void* const* d_in, const int* in_sizes, int n_in,
                              void* d_out, int out_size) {
    const float* x  = (const float*)d_in[0];
    const void*  he = d_in[1];
    const float* W1 = (const float*)d_in[2];
    const float* b1 = (const float*)d_in[3];
    const float* W2 = (const float*)d_in[4];
    const float* b2 = (const float*)d_in[5];
    const float* Wp = (const float*)d_in[6];
    const float* bp = (const float*)d_in[7];

    float* out  = (float*)d_out;
    float* zout = out;                                  // [N, 64]
    float* f1   = out + (size_t)N_NODES * OUT_C;        // [N, 128]
    float* f2   = f1  + (size_t)N_NODES * HID_C;        // [N, 64]

    const int T = 256;
    auto blocks = [](long long n, int t) { return (int)((n + t - 1) / t); };
    const int gemm_grid = (N_NODES + 63) / 64;

    // dtype detection: sample first 2048 8-byte words (safe: buffer >= 6.4MB)
    init_flag_kernel<<<1, 1>>>();
    detect_dtype_kernel<<<8, 256>>>(he);

    // degrees (shared by both layers)
    zero_deg_kernel<<<blocks(N_NODES, T), T>>>();
    deg_kernel<<<blocks(NNZ, T), T>>>(he);

    // ---- layer 1: F = 128 ----
    gemm_kernel<IN_C, HID_C, true><<<gemm_grid, 256>>>(x, W1, nullptr, nullptr, N_NODES);
    zero_m_kernel<HID_C><<<blocks((long long)N_EDGES * HID_C, T), T>>>();
    scatter_ne<HID_C><<<blocks((long long)NNZ * (HID_C / 4), T), T>>>(he);
    zero_acc_kernel<HID_C><<<blocks((long long)N_NODES * HID_C, T), T>>>();
    scatter_en<HID_C><<<blocks((long long)NNZ * (HID_C / 4), T), T>>>(he);
    finalize_kernel<HID_C><<<blocks((long long)N_NODES * HID_C, T), T>>>(b1, f1);

    // ---- layer 2: F = 64 ----
    gemm_kernel<HID_C, OUT_C, true><<<gemm_grid, 256>>>(f1, W2, nullptr, nullptr, N_NODES);
    zero_m_kernel<OUT_C><<<blocks((long long)N_EDGES * OUT_C, T), T>>>();
    scatter_ne<OUT_C><<<blocks((long long)NNZ * (OUT_C / 4), T), T>>>(he);
    zero_acc_kernel<OUT_C><<<blocks((long long)N_NODES * OUT_C, T), T>>>();
    scatter_en<OUT_C><<<blocks((long long)NNZ * (OUT_C / 4), T), T>>>(he);
    finalize_kernel<OUT_C><<<blocks((long long)N_NODES * OUT_C, T), T>>>(b2, f2);

    // ---- projection head: z = f2 @ Wp + bp ----
    gemm_kernel<OUT_C, OUT_C, false><<<gemm_grid, 256>>>(f2, Wp, bp, zout, N_NODES);
}

// round 4
// speedup vs baseline: 2.0520x; 2.0520x over previous
#include <cuda_runtime.h>

#define N_NODES 50000
#define N_EDGES 50000
#define NNZ     800000
#define IN_C    256
#define HID_C   128
#define OUT_C   64

// ---------------- scratch (device globals; referenced by name only) ----------------
__device__ float g_xw [N_NODES * HID_C];   // X@W1 ; reused as f1@W2 (N x 64)
__device__ float g_m  [N_EDGES * HID_C];   // per-edge rows
__device__ int   g_ecnt[N_EDGES];          // edge sizes
__device__ int   g_ncnt[N_NODES];          // node degrees
__device__ int   g_eoff[N_EDGES + 1];      // CSR offsets (by edge)
__device__ int   g_noff[N_NODES + 1];      // CSR offsets (by node)
__device__ int   g_ecur[N_EDGES];          // fill cursors
__device__ int   g_ncur[N_NODES];
__device__ int   g_eadj[NNZ];              // node ids grouped by edge
__device__ int   g_nadj[NNZ];              // edge ids grouped by node
__device__ int   g_is64;                   // 1 if hyperedge_index is int64

// ---------------- index dtype detection ----------------
__global__ void init_flag_kernel() { g_is64 = 1; }

__global__ void detect_dtype_kernel(const void* he) {
    __shared__ int bad;
    if (threadIdx.x == 0) bad = 0;
    __syncthreads();
    const long long* p = (const long long*)he;
    long long v = p[threadIdx.x + blockDim.x * blockIdx.x];
    if (v < 0 || v >= (long long)N_EDGES) atomicOr(&bad, 1);
    __syncthreads();
    if (threadIdx.x == 0 && bad) atomicExch(&g_is64, 0);
}

__device__ __forceinline__ int idx_node(const void* he, int i) {
    if (g_is64) return (int)((const long long*)he)[i];
    return ((const int*)he)[i];
}
__device__ __forceinline__ int idx_edge(const void* he, int i) {
    if (g_is64) return (int)((const long long*)he)[NNZ + i];
    return ((const int*)he)[NNZ + i];
}

// ---------------- CSR build ----------------
__global__ void zero_counts_kernel() {
    int i = blockIdx.x * blockDim.x + threadIdx.x;
    if (i < N_EDGES) { g_ecnt[i] = 0; g_ecur[i] = 0; }
    if (i < N_NODES) { g_ncnt[i] = 0; g_ncur[i] = 0; }
}

__global__ void hist_kernel(const void* __restrict__ he) {
    int i = blockIdx.x * blockDim.x + threadIdx.x;
    if (i < NNZ) {
        int n = idx_node(he, i);
        int e = idx_edge(he, i);
        if ((unsigned)n < N_NODES) atomicAdd(&g_ncnt[n], 1);
        if ((unsigned)e < N_EDGES) atomicAdd(&g_ecnt[e], 1);
    }
}

// single-block exclusive scan of both count arrays (Hillis-Steele, chunks of 1024)
__global__ void scan_kernel() {
    __shared__ int sh[1024];
    const int tid = threadIdx.x;

    // --- edges ---
    int carry = 0;
    for (int base = 0; base < N_EDGES; base += 1024) {
        int i = base + tid;
        int v = (i < N_EDGES) ? g_ecnt[i] : 0;
        sh[tid] = v;
        __syncthreads();
        #pragma unroll
        for (int off = 1; off < 1024; off <<= 1) {
            int t = (tid >= off) ? sh[tid - off] : 0;
            __syncthreads();
            sh[tid] += t;
            __syncthreads();
        }
        if (i < N_EDGES) {
            g_eoff[i] = carry + sh[tid] - v;
            if (i == N_EDGES - 1) g_eoff[N_EDGES] = carry + sh[tid];
        }
        carry += sh[1023];
        __syncthreads();
    }

    // --- nodes ---
    carry = 0;
    for (int base = 0; base < N_NODES; base += 1024) {
        int i = base + tid;
        int v = (i < N_NODES) ? g_ncnt[i] : 0;
        sh[tid] = v;
        __syncthreads();
        #pragma unroll
        for (int off = 1; off < 1024; off <<= 1) {
            int t = (tid >= off) ? sh[tid - off] : 0;
            __syncthreads();
            sh[tid] += t;
            __syncthreads();
        }
        if (i < N_NODES) {
            g_noff[i] = carry + sh[tid] - v;
            if (i == N_NODES - 1) g_noff[N_NODES] = carry + sh[tid];
        }
        carry += sh[1023];
        __syncthreads();
    }
}

__global__ void perm_kernel(const void* __restrict__ he) {
    int i = blockIdx.x * blockDim.x + threadIdx.x;
    if (i >= NNZ) return;
    int n = idx_node(he, i);
    int e = idx_edge(he, i);
    if ((unsigned)n >= N_NODES || (unsigned)e >= N_EDGES) return;
    int pe = g_eoff[e] + atomicAdd(&g_ecur[e], 1);
    g_eadj[pe] = n;
    int pn = g_noff[n] + atomicAdd(&g_ncur[n], 1);
    g_nadj[pn] = e;
}

// ---------------- warp-per-row gather aggregation ----------------
// dst[row] = (sum over members src[adj]) * 1/cnt  [+bias, relu]
template<int F, bool RELU>
__global__ void gather_rows(const float* __restrict__ src,
                            const int* __restrict__ adj,
                            const int* __restrict__ off,
                            const float* __restrict__ bias,
                            float* __restrict__ dst, int nrows) {
    constexpr int VEC = F / 32;           // 4 for F=128, 2 for F=64
    int warp = (blockIdx.x * blockDim.x + threadIdx.x) >> 5;
    int lane = threadIdx.x & 31;
    if (warp >= nrows) return;

    int s = off[warp];
    int e = off[warp + 1];

    float acc[VEC];
    #pragma unroll
    for (int k = 0; k < VEC; k++) acc[k] = 0.0f;

    for (int j = s; j < e; j++) {
        int r = adj[j];
        const float* p = src + (size_t)r * F + lane * VEC;
        if (VEC == 4) {
            float4 v = *reinterpret_cast<const float4*>(p);
            acc[0] += v.x; acc[1] += v.y;
            if (VEC > 2) { acc[VEC > 2 ? 2 : 0] += v.z; acc[VEC > 3 ? 3 : 0] += v.w; }
        } else {
            float2 v = *reinterpret_cast<const float2*>(p);
            acc[0] += v.x; acc[1] += v.y;
        }
    }

    float inv = (e > s) ? (1.0f / (float)(e - s)) : 0.0f;
    float* d = dst + (size_t)warp * F + lane * VEC;

    if (VEC == 4) {
        float4 o;
        if (RELU) {
            o.x = fmaxf(fmaf(acc[0], inv, bias[lane * 4 + 0]), 0.0f);
            o.y = fmaxf(fmaf(acc[1], inv, bias[lane * 4 + 1]), 0.0f);
            o.z = fmaxf(fmaf(acc[VEC > 2 ? 2 : 0], inv, bias[lane * 4 + 2]), 0.0f);
            o.w = fmaxf(fmaf(acc[VEC > 3 ? 3 : 0], inv, bias[lane * 4 + 3]), 0.0f);
        } else {
            o.x = acc[0] * inv; o.y = acc[1] * inv;
            o.z = acc[VEC > 2 ? 2 : 0] * inv; o.w = acc[VEC > 3 ? 3 : 0] * inv;
        }
        *reinterpret_cast<float4*>(d) = o;
    } else {
        float2 o;
        if (RELU) {
            o.x = fmaxf(fmaf(acc[0], inv, bias[lane * 2 + 0]), 0.0f);
            o.y = fmaxf(fmaf(acc[1], inv, bias[lane * 2 + 1]), 0.0f);
        } else {
            o.x = acc[0] * inv; o.y = acc[1] * inv;
        }
        *reinterpret_cast<float2*>(d) = o;
    }
}

// ---------------- register-tiled SGEMM: C[M,N] = A[M,K] @ B[K,N] (+bias) ----------
template<int K, int N, bool TO_XW>
__global__ void gemm_kernel(const float* __restrict__ A, const float* __restrict__ B,
                            const float* __restrict__ bias, float* __restrict__ C, int M) {
    constexpr int BM = 64, BK = 32;
    constexpr int TM = 4;
    constexpr int TN = N / 16;            // 8 for N=128, 4 for N=64
    __shared__ float As[BK][BM + 4];
    __shared__ float Bs[BK][N];

    const int tid = threadIdx.x;          // 256 threads
    const int tx = tid & 15;
    const int ty = tid >> 4;
    const int blockRow = blockIdx.x * BM;

    float* Cp = TO_XW ? g_xw : C;

    float acc[TM][TN];
    #pragma unroll
    for (int i = 0; i < TM; i++)
        #pragma unroll
        for (int j = 0; j < TN; j++) acc[i][j] = 0.0f;

    for (int k0 = 0; k0 < K; k0 += BK) {
        #pragma unroll
        for (int l = 0; l < 2; l++) {
            int idx = tid + l * 256;
            int r = idx >> 3;
            int c = (idx & 7) * 4;
            int grow = blockRow + r;
            float4 v = make_float4(0.f, 0.f, 0.f, 0.f);
            if (grow < M)
                v = *reinterpret_cast<const float4*>(A + (size_t)grow * K + k0 + c);
            As[c + 0][r] = v.x; As[c + 1][r] = v.y;
            As[c + 2][r] = v.z; As[c + 3][r] = v.w;
        }
        constexpr int BF4 = BK * N / 4;
        #pragma unroll
        for (int l = 0; l < BF4 / 256; l++) {
            int idx = tid + l * 256;
            int r = idx / (N / 4);
            int c = (idx % (N / 4)) * 4;
            *reinterpret_cast<float4*>(&Bs[r][c]) =
                *reinterpret_cast<const float4*>(B + (size_t)(k0 + r) * N + c);
        }
        __syncthreads();

        #pragma unroll
        for (int k = 0; k < BK; k++) {
            float a[TM], b[TN];
            #pragma unroll
            for (int i = 0; i < TM; i++) a[i] = As[k][i * 16 + ty];
            #pragma unroll
            for (int j = 0; j < TN; j++) b[j] = Bs[k][tx * TN + j];
            #pragma unroll
            for (int i = 0; i < TM; i++)
                #pragma unroll
                for (int j = 0; j < TN; j++)
                    acc[i][j] = fmaf(a[i], b[j], acc[i][j]);
        }
        __syncthreads();
    }

    #pragma unroll
    for (int i = 0; i < TM; i++) {
        int row = blockRow + i * 16 + ty;
        if (row >= M) continue;
        #pragma unroll
        for (int j = 0; j < TN; j += 4) {
            int col = tx * TN + j;
            float4 v;
            v.x = acc[i][j + 0]; v.y = acc[i][j + 1];
            v.z = acc[i][j + 2]; v.w = acc[i][j + 3];
            if (bias) {
                v.x += bias[col + 0]; v.y += bias[col + 1];
                v.z += bias[col + 2]; v.w += bias[col + 3];
            }
            *reinterpret_cast<float4*>(Cp + (size_t)row * N + col) = v;
        }
    }
}

// device-global accessor kernels avoid host symbol queries: gather reads/writes
// g_xw / g_m through wrapper kernels parameterized by small enums.
template<int F, bool RELU, int SRC_SEL, int DST_SEL>
__global__ void gather_rows_g(const int* __restrict__ adj,
                              const int* __restrict__ off,
                              const float* __restrict__ bias,
                              float* __restrict__ dst_param, int nrows);

// SRC_SEL: 0 = g_xw, 1 = g_m.  DST_SEL: 0 = g_m, 1 = param.
template<int F, bool RELU, int SRC_SEL, int DST_SEL>
__global__ void gather_rows_g(const int* __restrict__ adj,
                              const int* __restrict__ off,
                              const float* __restrict__ bias,
                              float* __restrict__ dst_param, int nrows) {
    constexpr int VEC = F / 32;
    int warp = (blockIdx.x * blockDim.x + threadIdx.x) >> 5;
    int lane = threadIdx.x & 31;
    if (warp >= nrows) return;

    const float* src = (SRC_SEL == 0) ? g_xw : g_m;
    float* dst = (DST_SEL == 0) ? g_m : dst_param;

    int s = off[warp];
    int e = off[warp + 1];

    float acc[VEC];
    #pragma unroll
    for (int k = 0; k < VEC; k++) acc[k] = 0.0f;

    int j = s;
    for (; j + 1 < e; j += 2) {          // unroll x2 for MLP
        int r0 = adj[j], r1 = adj[j + 1];
        const float4* p0 = reinterpret_cast<const float4*>(src + (size_t)r0 * F + lane * VEC);
        const float4* p1 = reinterpret_cast<const float4*>(src + (size_t)r1 * F + lane * VEC);
        if (VEC == 4) {
            float4 v0 = *p0, v1 = *p1;
            acc[0] += v0.x + v1.x; acc[1] += v0.y + v1.y;
            acc[VEC > 2 ? 2 : 0] += v0.z + v1.z; acc[VEC > 3 ? 3 : 0] += v0.w + v1.w;
        } else {
            float2 v0 = *reinterpret_cast<const float2*>(src + (size_t)r0 * F + lane * VEC);
            float2 v1 = *reinterpret_cast<const float2*>(src + (size_t)r1 * F + lane * VEC);
            acc[0] += v0.x + v1.x; acc[1] += v0.y + v1.y;
        }
    }
    if (j < e) {
        int r = adj[j];
        if (VEC == 4) {
            float4 v = *reinterpret_cast<const float4*>(src + (size_t)r * F + lane * VEC);
            acc[0] += v.x; acc[1] += v.y;
            acc[VEC > 2 ? 2 : 0] += v.z; acc[VEC > 3 ? 3 : 0] += v.w;
        } else {
            float2 v = *reinterpret_cast<const float2*>(src + (size_t)r * F + lane * VEC);
            acc[0] += v.x; acc[1] += v.y;
        }
    }

    float inv = (e > s) ? (1.0f / (float)(e - s)) : 0.0f;
    float* d = dst + (size_t)warp * F + lane * VEC;

    if (VEC == 4) {
        float4 o;
        float b0 = RELU ? bias[lane * 4 + 0] : 0.f, b1 = RELU ? bias[lane * 4 + 1] : 0.f;
        float b2 = RELU ? bias[lane * 4 + 2] : 0.f, b3 = RELU ? bias[lane * 4 + 3] : 0.f;
        o.x = RELU ? fmaxf(fmaf(acc[0], inv, b0), 0.f) : acc[0] * inv;
        o.y = RELU ? fmaxf(fmaf(acc[1], inv, b1), 0.f) : acc[1] * inv;
        o.z = RELU ? fmaxf(fmaf(acc[VEC > 2 ? 2 : 0], inv, b2), 0.f) : acc[VEC > 2 ? 2 : 0] * inv;
        o.w = RELU ? fmaxf(fmaf(acc[VEC > 3 ? 3 : 0], inv, b3), 0.f) : acc[VEC > 3 ? 3 : 0] * inv;
        *reinterpret_cast<float4*>(d) = o;
    } else {
        float2 o;
        float b0 = RELU ? bias[lane * 2 + 0] : 0.f, b1 = RELU ? bias[lane * 2 + 1] : 0.f;
        o.x = RELU ? fmaxf(fmaf(acc[0], inv, b0), 0.f) : acc[0] * inv;
        o.y = RELU ? fmaxf(fmaf(acc[1], inv, b1), 0.f) : acc[1] * inv;
        *reinterpret_cast<float2*>(d) = o;
    }
}

// expose device-global pointers to launch code via tiny copy kernels is not
// allowed (no alloc) — instead gather_rows_g handles g_* selection internally,
// and offsets/adjacency are passed via device-global-decayed pointers obtained
// inside kernels. For off/adj params we use wrapper kernels below.
__global__ void run_gather_e128() {}

extern "C" void kernel_launch(void* const* d_in, const int* in_sizes, int n_in,
                              void* d_out, int out_size) {
    const float* x  = (const float*)d_in[0];
    const void*  he = d_in[1];
    const float* W1 = (const float*)d_in[2];
    const float* b1 = (const float*)d_in[3];
    const float* W2 = (const float*)d_in[4];
    const float* b2 = (const float*)d_in[5];
    const float* Wp = (const float*)d_in[6];
    const float* bp = (const float*)d_in[7];

    float* out  = (float*)d_out;
    float* zout = out;                                  // [N, 64]
    float* f1   = out + (size_t)N_NODES * OUT_C;        // [N, 128]
    float* f2   = f1  + (size_t)N_NODES * HID_C;        // [N, 64]

    const int T = 256;
    auto blocks = [](long long n, int t) { return (int)((n + t - 1) / t); };
    const int gemm_grid = (N_NODES + 63) / 64;
    const int gather_grid = (N_NODES * 32 + T - 1) / T;   // warp per row, 50000 rows

    // device-global array addresses: legal to take on host only via kernels,
    // so pass them through kernel params using the "address-of in device code"
    // pattern: we get them with cudaGetSymbolAddress-free trick — simply
    // declare wrapper launches where adj/off are read from globals inside.
    // (gather_rows_g reads g_xw/g_m internally; adj/off passed as params
    //  obtained below via cudaGetSymbolAddress is NOT used.)

    // dtype detection
    init_flag_kernel<<<1, 1>>>();
    detect_dtype_kernel<<<8, 256>>>(he);

    // CSR build
    zero_counts_kernel<<<blocks(N_EDGES, T), T>>>();
    hist_kernel<<<blocks(NNZ, T), T>>>(he);
    scan_kernel<<<1, 1024>>>();
    perm_kernel<<<blocks(NNZ, T), T>>>(he);

    // pointers to device globals for adj/off params: use static device-side
    // fetch — cudaGetSymbolAddress is host API and allocation-free; it was
    // NOT the cause of the earlier trap (dtype was). Use it.
    int *p_eoff, *p_noff, *p_eadj, *p_nadj;
    cudaGetSymbolAddress((void**)&p_eoff, g_eoff);
    cudaGetSymbolAddress((void**)&p_noff, g_noff);
    cudaGetSymbolAddress((void**)&p_eadj, g_eadj);
    cudaGetSymbolAddress((void**)&p_nadj, g_nadj);

    // ---- layer 1: F = 128 ----
    gemm_kernel<IN_C, HID_C, true><<<gemm_grid, 256>>>(x, W1, nullptr, nullptr, N_NODES);
    // node -> edge (src g_xw, dst g_m), Binv fused
    gather_rows_g<HID_C, false, 0, 0><<<gather_grid, T>>>(p_eadj, p_eoff, nullptr, nullptr, N_EDGES);
    // edge -> node (src g_m, dst f1), Dinv + bias + relu fused
    gather_rows_g<HID_C, true, 1, 1><<<gather_grid, T>>>(p_nadj, p_noff, b1, f1, N_NODES);

    // ---- layer 2: F = 64 ----
    gemm_kernel<HID_C, OUT_C, true><<<gemm_grid, 256>>>(f1, W2, nullptr, nullptr, N_NODES);
    gather_rows_g<OUT_C, false, 0, 0><<<gather_grid, T>>>(p_eadj, p_eoff, nullptr, nullptr, N_EDGES);
    gather_rows_g<OUT_C, true, 1, 1><<<gather_grid, T>>>(p_nadj, p_noff, b2, f2, N_NODES);

    // ---- projection head: z = f2 @ Wp + bp ----
    gemm_kernel<OUT_C, OUT_C, false><<<gemm_grid, 256>>>(f2, Wp, bp, zout, N_NODES);
}

// round 5
// speedup vs baseline: 3.4506x; 1.6816x over previous
#include <cuda_runtime.h>

#define N_NODES 50000
#define N_EDGES 50000
#define NNZ     800000
#define IN_C    256
#define HID_C   128
#define OUT_C   64

typedef unsigned long long ull;

// ---------------- scratch (device globals) ----------------
__device__ float g_xw [N_NODES * HID_C];   // X@W1 ; reused as f1@W2 (N x 64)
__device__ float g_m  [N_EDGES * HID_C];   // per-edge rows
__device__ int   g_ecnt[N_EDGES];
__device__ int   g_ncnt[N_NODES];
__device__ int   g_eoff[N_EDGES + 1];
__device__ int   g_noff[N_NODES + 1];
__device__ int   g_ecur[N_EDGES];
__device__ int   g_ncur[N_NODES];
__device__ int   g_eadj[NNZ];
__device__ int   g_nadj[NNZ];
__device__ int   g_bsum[2][64];
__device__ int   g_is64;

// ---------------- f32x2 helpers ----------------
__device__ __forceinline__ ull dup2(float v) {
    ull r; asm("mov.b64 %0, {%1, %1};" : "=l"(r) : "f"(v)); return r;
}
__device__ __forceinline__ void fma2(ull& d, ull a, ull b) {
    asm("fma.rn.f32x2 %0, %1, %2, %0;" : "+l"(d) : "l"(a), "l"(b));
}
__device__ __forceinline__ void unpack2(ull v, float& lo, float& hi) {
    asm("mov.b64 {%0, %1}, %2;" : "=f"(lo), "=f"(hi) : "l"(v));
}

// ---------------- index dtype detection ----------------
__global__ void init_flag_kernel() { g_is64 = 1; }

__global__ void detect_dtype_kernel(const void* he) {
    __shared__ int bad;
    if (threadIdx.x == 0) bad = 0;
    __syncthreads();
    const long long* p = (const long long*)he;
    long long v = p[threadIdx.x + blockDim.x * blockIdx.x];
    if (v < 0 || v >= (long long)N_EDGES) atomicOr(&bad, 1);
    __syncthreads();
    if (threadIdx.x == 0 && bad) atomicExch(&g_is64, 0);
}

__device__ __forceinline__ int idx_node(const void* he, int i) {
    if (g_is64) return (int)((const long long*)he)[i];
    return ((const int*)he)[i];
}
__device__ __forceinline__ int idx_edge(const void* he, int i) {
    if (g_is64) return (int)((const long long*)he)[NNZ + i];
    return ((const int*)he)[NNZ + i];
}

// ---------------- CSR build ----------------
__global__ void zero_counts_kernel() {
    int i = blockIdx.x * blockDim.x + threadIdx.x;
    if (i < N_EDGES) { g_ecnt[i] = 0; g_ecur[i] = 0; }
    if (i < N_NODES) { g_ncnt[i] = 0; g_ncur[i] = 0; }
}

__global__ void hist_kernel(const void* __restrict__ he) {
    int i = blockIdx.x * blockDim.x + threadIdx.x;
    if (i < NNZ) {
        int n = idx_node(he, i);
        int e = idx_edge(he, i);
        if ((unsigned)n < N_NODES) atomicAdd(&g_ncnt[n], 1);
        if ((unsigned)e < N_EDGES) atomicAdd(&g_ecnt[e], 1);
    }
}

// SEL: 0 = edges (g_ecnt/g_eoff), 1 = nodes
template<int SEL>
__global__ void scan_reduce() {
    const int n = SEL ? N_NODES : N_EDGES;
    int i = blockIdx.x * 1024 + threadIdx.x;
    int v = 0;
    if (i < n) v = SEL ? g_ncnt[i] : g_ecnt[i];
    #pragma unroll
    for (int o = 16; o > 0; o >>= 1) v += __shfl_down_sync(~0u, v, o);
    __shared__ int ws[32];
    int lane = threadIdx.x & 31, w = threadIdx.x >> 5;
    if (lane == 0) ws[w] = v;
    __syncthreads();
    if (w == 0) {
        int t = ws[lane];
        #pragma unroll
        for (int o = 16; o > 0; o >>= 1) t += __shfl_down_sync(~0u, t, o);
        if (lane == 0) g_bsum[SEL][blockIdx.x] = t;
    }
}

__global__ void scan_partials() {   // 1 block, 128 threads; both SELs
    int sel = threadIdx.x >> 6;
    int t = threadIdx.x & 63;
    __shared__ int sh[2][64];
    int v = (t < 49) ? g_bsum[sel][t] : 0;
    sh[sel][t] = v;
    __syncthreads();
    #pragma unroll
    for (int o = 1; o < 64; o <<= 1) {
        int u = (t >= o) ? sh[sel][t - o] : 0;
        __syncthreads();
        sh[sel][t] += u;
        __syncthreads();
    }
    if (t < 49) g_bsum[sel][t] = sh[sel][t] - v;   // exclusive
}

template<int SEL>
__global__ void scan_apply() {
    const int n = SEL ? N_NODES : N_EDGES;
    int i = blockIdx.x * 1024 + threadIdx.x;
    int lane = threadIdx.x & 31, w = threadIdx.x >> 5;
    int v = 0;
    if (i < n) v = SEL ? g_ncnt[i] : g_ecnt[i];
    int s = v;
    #pragma unroll
    for (int o = 1; o < 32; o <<= 1) {
        int t = __shfl_up_sync(~0u, s, o);
        if (lane >= o) s += t;
    }
    __shared__ int wsum[32], wexc[32];
    if (lane == 31) wsum[w] = s;
    __syncthreads();
    if (w == 0) {
        int t = wsum[lane];
        int q = t;
        #pragma unroll
        for (int o = 1; o < 32; o <<= 1) {
            int u = __shfl_up_sync(~0u, q, o);
            if (lane >= o) q += u;
        }
        wexc[lane] = q - t;
    }
    __syncthreads();
    int excl = s - v + wexc[w] + g_bsum[SEL][blockIdx.x];
    if (i < n) {
        if (SEL) g_noff[i] = excl; else g_eoff[i] = excl;
        if (i == n - 1) { if (SEL) g_noff[n] = excl + v; else g_eoff[n] = excl + v; }
    }
}

__global__ void perm_kernel(const void* __restrict__ he) {
    int i = blockIdx.x * blockDim.x + threadIdx.x;
    if (i >= NNZ) return;
    int n = idx_node(he, i);
    int e = idx_edge(he, i);
    if ((unsigned)n >= N_NODES || (unsigned)e >= N_EDGES) return;
    int pe = g_eoff[e] + atomicAdd(&g_ecur[e], 1);
    g_eadj[pe] = n;
    int pn = g_noff[n] + atomicAdd(&g_ncur[n], 1);
    g_nadj[pn] = e;
}

// ---------------- warp-per-row gather, unroll x4 ----------------
// SRC_SEL: 0 = g_xw, 1 = g_m.  DST_SEL: 0 = g_m, 1 = param.
template<int F, bool RELU, int SRC_SEL, int DST_SEL>
__global__ void gather_rows_g(const int* __restrict__ adj,
                              const int* __restrict__ off,
                              const float* __restrict__ bias,
                              float* __restrict__ dst_param, int nrows) {
    constexpr int VEC = F / 32;           // 4 or 2
    int warp = (blockIdx.x * blockDim.x + threadIdx.x) >> 5;
    int lane = threadIdx.x & 31;
    if (warp >= nrows) return;

    const float* src = (SRC_SEL == 0) ? g_xw : g_m;
    float* dst = (DST_SEL == 0) ? g_m : dst_param;

    int s = off[warp];
    int e = off[warp + 1];

    float acc[VEC];
    #pragma unroll
    for (int k = 0; k < VEC; k++) acc[k] = 0.0f;

    int j = s;
    for (; j + 3 < e; j += 4) {
        int r0 = adj[j], r1 = adj[j+1], r2 = adj[j+2], r3 = adj[j+3];
        if (VEC == 4) {
            float4 v0 = *reinterpret_cast<const float4*>(src + (size_t)r0 * F + lane * 4);
            float4 v1 = *reinterpret_cast<const float4*>(src + (size_t)r1 * F + lane * 4);
            float4 v2 = *reinterpret_cast<const float4*>(src + (size_t)r2 * F + lane * 4);
            float4 v3 = *reinterpret_cast<const float4*>(src + (size_t)r3 * F + lane * 4);
            acc[0] += (v0.x + v1.x) + (v2.x + v3.x);
            acc[1] += (v0.y + v1.y) + (v2.y + v3.y);
            acc[VEC>2?2:0] += (v0.z + v1.z) + (v2.z + v3.z);
            acc[VEC>3?3:0] += (v0.w + v1.w) + (v2.w + v3.w);
        } else {
            float2 v0 = *reinterpret_cast<const float2*>(src + (size_t)r0 * F + lane * 2);
            float2 v1 = *reinterpret_cast<const float2*>(src + (size_t)r1 * F + lane * 2);
            float2 v2 = *reinterpret_cast<const float2*>(src + (size_t)r2 * F + lane * 2);
            float2 v3 = *reinterpret_cast<const float2*>(src + (size_t)r3 * F + lane * 2);
            acc[0] += (v0.x + v1.x) + (v2.x + v3.x);
            acc[1] += (v0.y + v1.y) + (v2.y + v3.y);
        }
    }
    for (; j < e; j++) {
        int r = adj[j];
        if (VEC == 4) {
            float4 v = *reinterpret_cast<const float4*>(src + (size_t)r * F + lane * 4);
            acc[0] += v.x; acc[1] += v.y;
            acc[VEC>2?2:0] += v.z; acc[VEC>3?3:0] += v.w;
        } else {
            float2 v = *reinterpret_cast<const float2*>(src + (size_t)r * F + lane * 2);
            acc[0] += v.x; acc[1] += v.y;
        }
    }

    float inv = (e > s) ? (1.0f / (float)(e - s)) : 0.0f;
    float* d = dst + (size_t)warp * F + lane * VEC;

    if (VEC == 4) {
        float4 o;
        if (RELU) {
            o.x = fmaxf(fmaf(acc[0], inv, bias[lane*4+0]), 0.f);
            o.y = fmaxf(fmaf(acc[1], inv, bias[lane*4+1]), 0.f);
            o.z = fmaxf(fmaf(acc[VEC>2?2:0], inv, bias[lane*4+2]), 0.f);
            o.w = fmaxf(fmaf(acc[VEC>3?3:0], inv, bias[lane*4+3]), 0.f);
        } else {
            o.x = acc[0]*inv; o.y = acc[1]*inv;
            o.z = acc[VEC>2?2:0]*inv; o.w = acc[VEC>3?3:0]*inv;
        }
        *reinterpret_cast<float4*>(d) = o;
    } else {
        float2 o;
        if (RELU) {
            o.x = fmaxf(fmaf(acc[0], inv, bias[lane*2+0]), 0.f);
            o.y = fmaxf(fmaf(acc[1], inv, bias[lane*2+1]), 0.f);
        } else {
            o.x = acc[0]*inv; o.y = acc[1]*inv;
        }
        *reinterpret_cast<float2*>(d) = o;
    }
}

// ---------------- FFMA2 SGEMM: C[M,N] = A[M,K] @ B[K,N] (+bias) ----------------
// BM=128, BK=16, 256 threads (tx = tid&15 over N interleaved, ty = tid>>4 over M).
// Accumulators are packed fp32 pairs over adjacent M rows (fma.rn.f32x2).
// B is duplicated in smem as (b,b) ull; column mapping col = tx + 16*j keeps
// all shared loads conflict-free.
template<int K, int N, bool TO_XW>
__global__ void __launch_bounds__(256)
gemm_kernel(const float* __restrict__ A, const float* __restrict__ B,
            const float* __restrict__ bias, float* __restrict__ C, int M) {
    constexpr int BM = 128, BK = 16;
    constexpr int TN = N / 16;            // 8 for N=128, 4 for N=64
    __shared__ float As[BK][BM + 4];      // transposed A tile, 16B-aligned rows
    __shared__ ull   BsD[BK][N];          // duplicated B tile

    const int tid = threadIdx.x;
    const int tx = tid & 15;
    const int ty = tid >> 4;
    const int blockRow = blockIdx.x * BM;
    float* Cp = TO_XW ? g_xw : C;

    ull acc2[4][TN];
    #pragma unroll
    for (int p = 0; p < 4; p++)
        #pragma unroll
        for (int j = 0; j < TN; j++) acc2[p][j] = 0ull;

    for (int k0 = 0; k0 < K; k0 += BK) {
        // ---- A tile fill: 128 rows x 16 cols, transposed ----
        #pragma unroll
        for (int l = 0; l < 2; l++) {
            int idx = tid + l * 256;
            int r = idx >> 2;
            int c4 = (idx & 3) * 4;
            int grow = blockRow + r;
            float4 v = make_float4(0.f, 0.f, 0.f, 0.f);
            if (grow < M)
                v = *reinterpret_cast<const float4*>(A + (size_t)grow * K + k0 + c4);
            As[c4 + 0][r] = v.x; As[c4 + 1][r] = v.y;
            As[c4 + 2][r] = v.z; As[c4 + 3][r] = v.w;
        }
        // ---- B tile fill (duplicated), stride-32 cols: coalesced LDG.32,
        //      conflict-free STS.64 ----
        #pragma unroll
        for (int l = 0; l < BK / 8; l++) {
            int r = l * 8 + (tid >> 5);
            int c0 = tid & 31;
            #pragma unroll
            for (int q = 0; q < N / 32; q++) {
                float v = B[(size_t)(k0 + r) * N + c0 + 32 * q];
                BsD[r][c0 + 32 * q] = dup2(v);
            }
        }
        __syncthreads();

        #pragma unroll
        for (int k = 0; k < BK; k++) {
            ulonglong2 aA = *reinterpret_cast<const ulonglong2*>(&As[k][ty * 8]);
            ulonglong2 aB = *reinterpret_cast<const ulonglong2*>(&As[k][ty * 8 + 4]);
            ull ap[4] = { aA.x, aA.y, aB.x, aB.y };
            ull bp[TN];
            #pragma unroll
            for (int j = 0; j < TN; j++) bp[j] = BsD[k][tx + 16 * j];
            #pragma unroll
            for (int p = 0; p < 4; p++)
                #pragma unroll
                for (int j = 0; j < TN; j++)
                    fma2(acc2[p][j], ap[p], bp[j]);
        }
        __syncthreads();
    }

    // ---- epilogue: unpack pairs -> rows (2p, 2p+1) ----
    #pragma unroll
    for (int p = 0; p < 4; p++) {
        int r0 = blockRow + ty * 8 + 2 * p;
        int r1 = r0 + 1;
        float lo[TN], hi[TN];
        #pragma unroll
        for (int j = 0; j < TN; j++) unpack2(acc2[p][j], lo[j], hi[j]);
        if (bias) {
            #pragma unroll
            for (int j = 0; j < TN; j++) {
                float b = bias[tx + 16 * j];
                lo[j] += b; hi[j] += b;
            }
        }
        if (r0 < M) {
            #pragma unroll
            for (int j = 0; j < TN; j++) Cp[(size_t)r0 * N + tx + 16 * j] = lo[j];
        }
        if (r1 < M) {
            #pragma unroll
            for (int j = 0; j < TN; j++) Cp[(size_t)r1 * N + tx + 16 * j] = hi[j];
        }
    }
}

// ---------------- launch ----------------
extern "C" void kernel_launch(void* const* d_in, const int* in_sizes, int n_in,
                              void* d_out, int out_size) {
    const float* x  = (const float*)d_in[0];
    const void*  he = d_in[1];
    const float* W1 = (const float*)d_in[2];
    const float* b1 = (const float*)d_in[3];
    const float* W2 = (const float*)d_in[4];
    const float* b2 = (const float*)d_in[5];
    const float* Wp = (const float*)d_in[6];
    const float* bp = (const float*)d_in[7];

    float* out  = (float*)d_out;
    float* zout = out;                                  // [N, 64]
    float* f1   = out + (size_t)N_NODES * OUT_C;        // [N, 128]
    float* f2   = f1  + (size_t)N_NODES * HID_C;        // [N, 64]

    const int T = 256;
    auto blocks = [](long long n, int t) { return (int)((n + t - 1) / t); };
    const int gemm_grid = (N_NODES + 127) / 128;
    const int gather_grid = (N_NODES * 32 + T - 1) / T;
    const int scan_grid = (N_NODES + 1023) / 1024;      // 49

    int *p_eoff, *p_noff, *p_eadj, *p_nadj;
    cudaGetSymbolAddress((void**)&p_eoff, g_eoff);
    cudaGetSymbolAddress((void**)&p_noff, g_noff);
    cudaGetSymbolAddress((void**)&p_eadj, g_eadj);
    cudaGetSymbolAddress((void**)&p_nadj, g_nadj);

    // dtype detection
    init_flag_kernel<<<1, 1>>>();
    detect_dtype_kernel<<<8, 256>>>(he);

    // CSR build
    zero_counts_kernel<<<blocks(N_EDGES, T), T>>>();
    hist_kernel<<<blocks(NNZ, T), T>>>(he);
    scan_reduce<0><<<scan_grid, 1024>>>();
    scan_reduce<1><<<scan_grid, 1024>>>();
    scan_partials<<<1, 128>>>();
    scan_apply<0><<<scan_grid, 1024>>>();
    scan_apply<1><<<scan_grid, 1024>>>();
    perm_kernel<<<blocks(NNZ, T), T>>>(he);

    // ---- layer 1: F = 128 ----
    gemm_kernel<IN_C, HID_C, true><<<gemm_grid, 256>>>(x, W1, nullptr, nullptr, N_NODES);
    gather_rows_g<HID_C, false, 0, 0><<<gather_grid, T>>>(p_eadj, p_eoff, nullptr, nullptr, N_EDGES);
    gather_rows_g<HID_C, true, 1, 1><<<gather_grid, T>>>(p_nadj, p_noff, b1, f1, N_NODES);

    // ---- layer 2: F = 64 ----
    gemm_kernel<HID_C, OUT_C, true><<<gemm_grid, 256>>>(f1, W2, nullptr, nullptr, N_NODES);
    gather_rows_g<OUT_C, false, 0, 0><<<gather_grid, T>>>(p_eadj, p_eoff, nullptr, nullptr, N_EDGES);
    gather_rows_g<OUT_C, true, 1, 1><<<gather_grid, T>>>(p_nadj, p_noff, b2, f2, N_NODES);

    // ---- projection head: z = f2 @ Wp + bp ----
    gemm_kernel<OUT_C, OUT_C, false><<<gemm_grid, 256>>>(f2, Wp, bp, zout, N_NODES);
}

// round 8
// speedup vs baseline: 3.6684x; 1.0631x over previous
#include <cuda_runtime.h>

#define N_NODES 50000
#define N_EDGES 50000
#define NNZ     800000
#define IN_C    256
#define HID_C   128
#define OUT_C   64

typedef unsigned long long ull;

// ---------------- scratch (device globals) ----------------
__device__ float g_xw [N_NODES * HID_C];   // X@W1 ; reused as f1@W2 (N x 64)
__device__ float g_m  [N_EDGES * HID_C];   // per-edge rows
__device__ int   g_ecnt[N_EDGES];
__device__ int   g_ncnt[N_NODES];
__device__ int   g_eoff[N_EDGES + 1];
__device__ int   g_noff[N_NODES + 1];
__device__ int   g_ecur[N_EDGES];
__device__ int   g_ncur[N_NODES];
__device__ int   g_eadj[NNZ];
__device__ int   g_nadj[NNZ];
__device__ int   g_bsum[2][64];
__device__ int   g_is64;

// ---------------- f32x2 helpers ----------------
__device__ __forceinline__ ull dup2(float v) {
    ull r; asm("mov.b64 %0, {%1, %1};" : "=l"(r) : "f"(v)); return r;
}
__device__ __forceinline__ void fma2(ull& d, ull a, ull b) {
    asm("fma.rn.f32x2 %0, %1, %2, %0;" : "+l"(d) : "l"(a), "l"(b));
}
__device__ __forceinline__ void unpack2(ull v, float& lo, float& hi) {
    asm("mov.b64 {%0, %1}, %2;" : "=f"(lo), "=f"(hi) : "l"(v));
}

// ---------------- index dtype detection ----------------
__global__ void detect_dtype_kernel(const void* he) {
    __shared__ int bad;
    if (threadIdx.x == 0) bad = 0;
    __syncthreads();
    const long long* p = (const long long*)he;
    long long v = p[threadIdx.x + blockDim.x * blockIdx.x];
    if (v < 0 || v >= (long long)N_EDGES) atomicOr(&bad, 1);
    __syncthreads();
    if (threadIdx.x == 0 && bad) atomicExch(&g_is64, 0);
}
__device__ __forceinline__ int idx_node(const void* he, int i) {
    if (g_is64) return (int)((const long long*)he)[i];
    return ((const int*)he)[i];
}
__device__ __forceinline__ int idx_edge(const void* he, int i) {
    if (g_is64) return (int)((const long long*)he)[NNZ + i];
    return ((const int*)he)[NNZ + i];
}

// ---------------- CSR build ----------------
__global__ void zero_counts_kernel() {
    int i = blockIdx.x * blockDim.x + threadIdx.x;
    if (i == 0) g_is64 = 1;
    if (i < N_EDGES) { g_ecnt[i] = 0; g_ecur[i] = 0; }
    if (i < N_NODES) { g_ncnt[i] = 0; g_ncur[i] = 0; }
}

#define SCAN_NB 49   // blocks of 1024 covering 50000

__global__ void scan_reduce_all() {
    int sel = (blockIdx.x >= SCAN_NB) ? 1 : 0;
    int b = blockIdx.x - sel * SCAN_NB;
    const int n = sel ? N_NODES : N_EDGES;
    int i = b * 1024 + threadIdx.x;
    int v = 0;
    if (i < n) v = sel ? g_ncnt[i] : g_ecnt[i];
    #pragma unroll
    for (int o = 16; o > 0; o >>= 1) v += __shfl_down_sync(~0u, v, o);
    __shared__ int ws[32];
    int lane = threadIdx.x & 31, w = threadIdx.x >> 5;
    if (lane == 0) ws[w] = v;
    __syncthreads();
    if (w == 0) {
        int t = ws[lane];
        #pragma unroll
        for (int o = 16; o > 0; o >>= 1) t += __shfl_down_sync(~0u, t, o);
        if (lane == 0) g_bsum[sel][b] = t;
    }
}

__global__ void scan_partials() {   // 1 block, 128 threads; both sels
    int sel = threadIdx.x >> 6;
    int t = threadIdx.x & 63;
    __shared__ int sh[2][64];
    int v = (t < SCAN_NB) ? g_bsum[sel][t] : 0;
    sh[sel][t] = v;
    __syncthreads();
    #pragma unroll
    for (int o = 1; o < 64; o <<= 1) {
        int u = (t >= o) ? sh[sel][t - o] : 0;
        __syncthreads();
        sh[sel][t] += u;
        __syncthreads();
    }
    if (t < SCAN_NB) g_bsum[sel][t] = sh[sel][t] - v;   // exclusive
}

__global__ void scan_apply_all() {
    int sel = (blockIdx.x >= SCAN_NB) ? 1 : 0;
    int b = blockIdx.x - sel * SCAN_NB;
    const int n = sel ? N_NODES : N_EDGES;
    int i = b * 1024 + threadIdx.x;
    int lane = threadIdx.x & 31, w = threadIdx.x >> 5;
    int v = 0;
    if (i < n) v = sel ? g_ncnt[i] : g_ecnt[i];
    int s = v;
    #pragma unroll
    for (int o = 1; o < 32; o <<= 1) {
        int t = __shfl_up_sync(~0u, s, o);
        if (lane >= o) s += t;
    }
    __shared__ int wsum[32], wexc[32];
    if (lane == 31) wsum[w] = s;
    __syncthreads();
    if (w == 0) {
        int t = wsum[lane];
        int q = t;
        #pragma unroll
        for (int o = 1; o < 32; o <<= 1) {
            int u = __shfl_up_sync(~0u, q, o);
            if (lane >= o) q += u;
        }
        wexc[lane] = q - t;
    }
    __syncthreads();
    int excl = s - v + wexc[w] + g_bsum[sel][b];
    if (i < n) {
        if (sel) g_noff[i] = excl; else g_eoff[i] = excl;
        if (i == n - 1) { if (sel) g_noff[n] = excl + v; else g_eoff[n] = excl + v; }
    }
}

__global__ void perm_kernel(const void* __restrict__ he) {
    int i = blockIdx.x * blockDim.x + threadIdx.x;
    if (i >= NNZ) return;
    int n = idx_node(he, i);
    int e = idx_edge(he, i);
    if ((unsigned)n >= N_NODES || (unsigned)e >= N_EDGES) return;
    int pe = g_eoff[e] + atomicAdd(&g_ecur[e], 1);
    g_eadj[pe] = n;
    int pn = g_noff[n] + atomicAdd(&g_ncur[n], 1);
    g_nadj[pn] = e;
}

// ---------------- fused: GEMM1 (blocks < G1_BLOCKS) + histogram (rest) ----------
// GEMM1: g_xw = X @ W1, M=N_NODES, K=256, N=128, FFMA2, BM=128, BK=16.
#define G1_BLOCKS ((N_NODES + 127) / 128)       // 391
#define HIST_BLOCKS ((NNZ + 255) / 256)         // 3125

__global__ void __launch_bounds__(256)
hist_gemm1_kernel(const void* __restrict__ he,
                  const float* __restrict__ X, const float* __restrict__ W1) {
    if (blockIdx.x >= G1_BLOCKS) {
        // ---- histogram path ----
        int i = (blockIdx.x - G1_BLOCKS) * 256 + threadIdx.x;
        if (i < NNZ) {
            int n = idx_node(he, i);
            int e = idx_edge(he, i);
            if ((unsigned)n < N_NODES) atomicAdd(&g_ncnt[n], 1);
            if ((unsigned)e < N_EDGES) atomicAdd(&g_ecnt[e], 1);
        }
        return;
    }

    // ---- GEMM1 path ----
    constexpr int K = IN_C, N = HID_C, BM = 128, BK = 16, TN = N / 16;
    __shared__ float As[BK][BM + 4];
    __shared__ ull   BsD[BK][N];

    const int tid = threadIdx.x;
    const int tx = tid & 15;
    const int ty = tid >> 4;
    const int blockRow = blockIdx.x * BM;

    ull acc2[4][TN];
    #pragma unroll
    for (int p = 0; p < 4; p++)
        #pragma unroll
        for (int j = 0; j < TN; j++) acc2[p][j] = 0ull;

    for (int k0 = 0; k0 < K; k0 += BK) {
        #pragma unroll
        for (int l = 0; l < 2; l++) {
            int idx = tid + l * 256;
            int r = idx >> 2;
            int c4 = (idx & 3) * 4;
            int grow = blockRow + r;
            float4 v = make_float4(0.f, 0.f, 0.f, 0.f);
            if (grow < N_NODES)
                v = *reinterpret_cast<const float4*>(X + (size_t)grow * K + k0 + c4);
            As[c4 + 0][r] = v.x; As[c4 + 1][r] = v.y;
            As[c4 + 2][r] = v.z; As[c4 + 3][r] = v.w;
        }
        #pragma unroll
        for (int l = 0; l < BK / 8; l++) {
            int r = l * 8 + (tid >> 5);
            int c0 = tid & 31;
            #pragma unroll
            for (int q = 0; q < N / 32; q++) {
                float v = W1[(size_t)(k0 + r) * N + c0 + 32 * q];
                BsD[r][c0 + 32 * q] = dup2(v);
            }
        }
        __syncthreads();

        #pragma unroll
        for (int k = 0; k < BK; k++) {
            ulonglong2 aA = *reinterpret_cast<const ulonglong2*>(&As[k][ty * 8]);
            ulonglong2 aB = *reinterpret_cast<const ulonglong2*>(&As[k][ty * 8 + 4]);
            ull ap[4] = { aA.x, aA.y, aB.x, aB.y };
            ull bp[TN];
            #pragma unroll
            for (int j = 0; j < TN; j++) bp[j] = BsD[k][tx + 16 * j];
            #pragma unroll
            for (int p = 0; p < 4; p++)
                #pragma unroll
                for (int j = 0; j < TN; j++)
                    fma2(acc2[p][j], ap[p], bp[j]);
        }
        __syncthreads();
    }

    #pragma unroll
    for (int p = 0; p < 4; p++) {
        int r0 = blockRow + ty * 8 + 2 * p;
        int r1 = r0 + 1;
        float lo[TN], hi[TN];
        #pragma unroll
        for (int j = 0; j < TN; j++) unpack2(acc2[p][j], lo[j], hi[j]);
        if (r0 < N_NODES) {
            #pragma unroll
            for (int j = 0; j < TN; j++) g_xw[(size_t)r0 * N + tx + 16 * j] = lo[j];
        }
        if (r1 < N_NODES) {
            #pragma unroll
            for (int j = 0; j < TN; j++) g_xw[(size_t)r1 * N + tx + 16 * j] = hi[j];
        }
    }
}

// ---------------- warp-per-row gather, unroll x4 ----------------
// SRC_SEL: 0 = g_xw, 1 = g_m.  DST_SEL: 0 = g_m, 1 = param.
template<int F, bool RELU, int SRC_SEL, int DST_SEL>
__global__ void gather_rows_g(const int* __restrict__ adj,
                              const int* __restrict__ off,
                              const float* __restrict__ bias,
                              float* __restrict__ dst_param, int nrows) {
    constexpr int VEC = F / 32;           // 4 or 2
    int warp = (blockIdx.x * blockDim.x + threadIdx.x) >> 5;
    int lane = threadIdx.x & 31;
    if (warp >= nrows) return;

    const float* src = (SRC_SEL == 0) ? g_xw : g_m;
    float* dst = (DST_SEL == 0) ? g_m : dst_param;

    int s = off[warp];
    int e = off[warp + 1];

    float acc[VEC];
    #pragma unroll
    for (int k = 0; k < VEC; k++) acc[k] = 0.0f;

    int j = s;
    for (; j + 3 < e; j += 4) {
        int r0 = adj[j], r1 = adj[j+1], r2 = adj[j+2], r3 = adj[j+3];
        if (VEC == 4) {
            float4 v0 = *reinterpret_cast<const float4*>(src + (size_t)r0 * F + lane * 4);
            float4 v1 = *reinterpret_cast<const float4*>(src + (size_t)r1 * F + lane * 4);
            float4 v2 = *reinterpret_cast<const float4*>(src + (size_t)r2 * F + lane * 4);
            float4 v3 = *reinterpret_cast<const float4*>(src + (size_t)r3 * F + lane * 4);
            acc[0] += (v0.x + v1.x) + (v2.x + v3.x);
            acc[1] += (v0.y + v1.y) + (v2.y + v3.y);
            acc[VEC>2?2:0] += (v0.z + v1.z) + (v2.z + v3.z);
            acc[VEC>3?3:0] += (v0.w + v1.w) + (v2.w + v3.w);
        } else {
            float2 v0 = *reinterpret_cast<const float2*>(src + (size_t)r0 * F + lane * 2);
            float2 v1 = *reinterpret_cast<const float2*>(src + (size_t)r1 * F + lane * 2);
            float2 v2 = *reinterpret_cast<const float2*>(src + (size_t)r2 * F + lane * 2);
            float2 v3 = *reinterpret_cast<const float2*>(src + (size_t)r3 * F + lane * 2);
            acc[0] += (v0.x + v1.x) + (v2.x + v3.x);
            acc[1] += (v0.y + v1.y) + (v2.y + v3.y);
        }
    }
    for (; j < e; j++) {
        int r = adj[j];
        if (VEC == 4) {
            float4 v = *reinterpret_cast<const float4*>(src + (size_t)r * F + lane * 4);
            acc[0] += v.x; acc[1] += v.y;
            acc[VEC>2?2:0] += v.z; acc[VEC>3?3:0] += v.w;
        } else {
            float2 v = *reinterpret_cast<const float2*>(src + (size_t)r * F + lane * 2);
            acc[0] += v.x; acc[1] += v.y;
        }
    }

    float inv = (e > s) ? (1.0f / (float)(e - s)) : 0.0f;
    float* d = dst + (size_t)warp * F + lane * VEC;

    if (VEC == 4) {
        float4 o;
        if (RELU) {
            o.x = fmaxf(fmaf(acc[0], inv, bias[lane*4+0]), 0.f);
            o.y = fmaxf(fmaf(acc[1], inv, bias[lane*4+1]), 0.f);
            o.z = fmaxf(fmaf(acc[VEC>2?2:0], inv, bias[lane*4+2]), 0.f);
            o.w = fmaxf(fmaf(acc[VEC>3?3:0], inv, bias[lane*4+3]), 0.f);
        } else {
            o.x = acc[0]*inv; o.y = acc[1]*inv;
            o.z = acc[VEC>2?2:0]*inv; o.w = acc[VEC>3?3:0]*inv;
        }
        *reinterpret_cast<float4*>(d) = o;
    } else {
        float2 o;
        if (RELU) {
            o.x = fmaxf(fmaf(acc[0], inv, bias[lane*2+0]), 0.f);
            o.y = fmaxf(fmaf(acc[1], inv, bias[lane*2+1]), 0.f);
        } else {
            o.x = acc[0]*inv; o.y = acc[1]*inv;
        }
        *reinterpret_cast<float2*>(d) = o;
    }
}

// ---------------- FFMA2 SGEMM (layers 2/3): C[M,N] = A[M,K] @ B[K,N] (+bias) ------
template<int K, int N, bool TO_XW>
__global__ void __launch_bounds__(256)
gemm_kernel(const float* __restrict__ A, const float* __restrict__ B,
            const float* __restrict__ bias, float* __restrict__ C, int M) {
    constexpr int BM = 128, BK = 16;
    constexpr int TN = N / 16;
    __shared__ float As[BK][BM + 4];
    __shared__ ull   BsD[BK][N];

    const int tid = threadIdx.x;
    const int tx = tid & 15;
    const int ty = tid >> 4;
    const int blockRow = blockIdx.x * BM;
    float* Cp = TO_XW ? g_xw : C;

    ull acc2[4][TN];
    #pragma unroll
    for (int p = 0; p < 4; p++)
        #pragma unroll
        for (int j = 0; j < TN; j++) acc2[p][j] = 0ull;

    for (int k0 = 0; k0 < K; k0 += BK) {
        #pragma unroll
        for (int l = 0; l < 2; l++) {
            int idx = tid + l * 256;
            int r = idx >> 2;
            int c4 = (idx & 3) * 4;
            int grow = blockRow + r;
            float4 v = make_float4(0.f, 0.f, 0.f, 0.f);
            if (grow < M)
                v = *reinterpret_cast<const float4*>(A + (size_t)grow * K + k0 + c4);
            As[c4 + 0][r] = v.x; As[c4 + 1][r] = v.y;
            As[c4 + 2][r] = v.z; As[c4 + 3][r] = v.w;
        }
        #pragma unroll
        for (int l = 0; l < BK / 8; l++) {
            int r = l * 8 + (tid >> 5);
            int c0 = tid & 31;
            #pragma unroll
            for (int q = 0; q < N / 32; q++) {
                float v = B[(size_t)(k0 + r) * N + c0 + 32 * q];
                BsD[r][c0 + 32 * q] = dup2(v);
            }
        }
        __syncthreads();

        #pragma unroll
        for (int k = 0; k < BK; k++) {
            ulonglong2 aA = *reinterpret_cast<const ulonglong2*>(&As[k][ty * 8]);
            ulonglong2 aB = *reinterpret_cast<const ulonglong2*>(&As[k][ty * 8 + 4]);
            ull ap[4] = { aA.x, aA.y, aB.x, aB.y };
            ull bp[TN];
            #pragma unroll
            for (int j = 0; j < TN; j++) bp[j] = BsD[k][tx + 16 * j];
            #pragma unroll
            for (int p = 0; p < 4; p++)
                #pragma unroll
                for (int j = 0; j < TN; j++)
                    fma2(acc2[p][j], ap[p], bp[j]);
        }
        __syncthreads();
    }

    #pragma unroll
    for (int p = 0; p < 4; p++) {
        int r0 = blockRow + ty * 8 + 2 * p;
        int r1 = r0 + 1;
        float lo[TN], hi[TN];
        #pragma unroll
        for (int j = 0; j < TN; j++) unpack2(acc2[p][j], lo[j], hi[j]);
        if (bias) {
            #pragma unroll
            for (int j = 0; j < TN; j++) {
                float b = bias[tx + 16 * j];
                lo[j] += b; hi[j] += b;
            }
        }
        if (r0 < M) {
            #pragma unroll
            for (int j = 0; j < TN; j++) Cp[(size_t)r0 * N + tx + 16 * j] = lo[j];
        }
        if (r1 < M) {
            #pragma unroll
            for (int j = 0; j < TN; j++) Cp[(size_t)r1 * N + tx + 16 * j] = hi[j];
        }
    }
}

// ---------------- launch ----------------
extern "C" void kernel_launch(void* const* d_in, const int* in_sizes, int n_in,
                              void* d_out, int out_size) {
    const float* x  = (const float*)d_in[0];
    const void*  he = d_in[1];
    const float* W1 = (const float*)d_in[2];
    const float* b1 = (const float*)d_in[3];
    const float* W2 = (const float*)d_in[4];
    const float* b2 = (const float*)d_in[5];
    const float* Wp = (const float*)d_in[6];
    const float* bp = (const float*)d_in[7];

    float* out  = (float*)d_out;
    float* zout = out;                                  // [N, 64]
    float* f1   = out + (size_t)N_NODES * OUT_C;        // [N, 128]
    float* f2   = f1  + (size_t)N_NODES * HID_C;        // [N, 64]

    const int T = 256;
    auto blocks = [](long long n, int t) { return (int)((n + t - 1) / t); };
    const int gemm_grid = (N_NODES + 127) / 128;        // 391
    const int gather_grid = (N_NODES * 32 + T - 1) / T;

    int *p_eoff, *p_noff, *p_eadj, *p_nadj;
    cudaGetSymbolAddress((void**)&p_eoff, g_eoff);
    cudaGetSymbolAddress((void**)&p_noff, g_noff);
    cudaGetSymbolAddress((void**)&p_eadj, g_eadj);
    cudaGetSymbolAddress((void**)&p_nadj, g_nadj);

    // CSR prep + dtype flag
    zero_counts_kernel<<<blocks(N_EDGES, T), T>>>();
    detect_dtype_kernel<<<8, 256>>>(he);

    // fused: GEMM1 (X@W1 -> g_xw) + histogram, concurrent on one grid
    hist_gemm1_kernel<<<G1_BLOCKS + HIST_BLOCKS, 256>>>(he, x, W1);

    // CSR finish
    scan_reduce_all<<<2 * SCAN_NB, 1024>>>();
    scan_partials<<<1, 128>>>();
    scan_apply_all<<<2 * SCAN_NB, 1024>>>();
    perm_kernel<<<blocks(NNZ, T), T>>>(he);

    // ---- layer 1: F = 128 ----
    gather_rows_g<HID_C, false, 0, 0><<<gather_grid, T>>>(p_eadj, p_eoff, nullptr, nullptr, N_EDGES);
    gather_rows_g<HID_C, true, 1, 1><<<gather_grid, T>>>(p_nadj, p_noff, b1, f1, N_NODES);

    // ---- layer 2: F = 64 ----
    gemm_kernel<HID_C, OUT_C, true><<<gemm_grid, 256>>>(f1, W2, nullptr, nullptr, N_NODES);
    gather_rows_g<OUT_C, false, 0, 0><<<gather_grid, T>>>(p_eadj, p_eoff, nullptr, nullptr, N_EDGES);
    gather_rows_g<OUT_C, true, 1, 1><<<gather_grid, T>>>(p_nadj, p_noff, b2, f2, N_NODES);

    // ---- projection head: z = f2 @ Wp + bp ----
    gemm_kernel<OUT_C, OUT_C, false><<<gemm_grid, 256>>>(f2, Wp, bp, zout, N_NODES);
}

// round 9
// speedup vs baseline: 3.8003x; 1.0360x over previous
#include <cuda_runtime.h>
#include <cuda_fp16.h>

#define N_NODES 50000
#define N_EDGES 50000
#define NNZ     800000
#define IN_C    256
#define HID_C   128
#define OUT_C   64

typedef unsigned long long ull;
typedef unsigned short ushort;

// ---------------- scratch (device globals) ----------------
__device__ ushort g_xwh[N_NODES * HID_C];  // X@W1 (fp16); reused as f1@W2 (N x 64)
__device__ ushort g_mh [N_EDGES * HID_C];  // per-edge rows (fp16)
__device__ int   g_ecnt[N_EDGES];
__device__ int   g_ncnt[N_NODES];
__device__ int   g_eoff[N_EDGES + 1];
__device__ int   g_noff[N_NODES + 1];
__device__ int   g_ecur[N_EDGES];
__device__ int   g_ncur[N_NODES];
__device__ int   g_eadj[NNZ];
__device__ int   g_nadj[NNZ];
__device__ int   g_bsum[2][64];
__device__ int   g_is64;

// ---------------- f32x2 helpers ----------------
__device__ __forceinline__ ull dup2(float v) {
    ull r; asm("mov.b64 %0, {%1, %1};" : "=l"(r) : "f"(v)); return r;
}
__device__ __forceinline__ void fma2(ull& d, ull a, ull b) {
    asm("fma.rn.f32x2 %0, %1, %2, %0;" : "+l"(d) : "l"(a), "l"(b));
}
__device__ __forceinline__ void unpack2(ull v, float& lo, float& hi) {
    asm("mov.b64 {%0, %1}, %2;" : "=f"(lo), "=f"(hi) : "l"(v));
}

// ---------------- index dtype detection ----------------
__global__ void detect_dtype_kernel(const void* he) {
    __shared__ int bad;
    if (threadIdx.x == 0) bad = 0;
    __syncthreads();
    const long long* p = (const long long*)he;
    long long v = p[threadIdx.x + blockDim.x * blockIdx.x];
    if (v < 0 || v >= (long long)N_EDGES) atomicOr(&bad, 1);
    __syncthreads();
    if (threadIdx.x == 0 && bad) atomicExch(&g_is64, 0);
}
__device__ __forceinline__ int idx_node(const void* he, int i) {
    if (g_is64) return (int)((const long long*)he)[i];
    return ((const int*)he)[i];
}
__device__ __forceinline__ int idx_edge(const void* he, int i) {
    if (g_is64) return (int)((const long long*)he)[NNZ + i];
    return ((const int*)he)[NNZ + i];
}

// ---------------- CSR build ----------------
__global__ void zero_counts_kernel() {
    int i = blockIdx.x * blockDim.x + threadIdx.x;
    if (i == 0) g_is64 = 1;
    if (i < N_EDGES) { g_ecnt[i] = 0; g_ecur[i] = 0; }
    if (i < N_NODES) { g_ncnt[i] = 0; g_ncur[i] = 0; }
}

#define SCAN_NB 49   // blocks of 1024 covering 50000

__global__ void scan_reduce_all() {
    int sel = (blockIdx.x >= SCAN_NB) ? 1 : 0;
    int b = blockIdx.x - sel * SCAN_NB;
    const int n = sel ? N_NODES : N_EDGES;
    int i = b * 1024 + threadIdx.x;
    int v = 0;
    if (i < n) v = sel ? g_ncnt[i] : g_ecnt[i];
    #pragma unroll
    for (int o = 16; o > 0; o >>= 1) v += __shfl_down_sync(~0u, v, o);
    __shared__ int ws[32];
    int lane = threadIdx.x & 31, w = threadIdx.x >> 5;
    if (lane == 0) ws[w] = v;
    __syncthreads();
    if (w == 0) {
        int t = ws[lane];
        #pragma unroll
        for (int o = 16; o > 0; o >>= 1) t += __shfl_down_sync(~0u, t, o);
        if (lane == 0) g_bsum[sel][b] = t;
    }
}

__global__ void scan_partials() {   // 1 block, 128 threads; both sels
    int sel = threadIdx.x >> 6;
    int t = threadIdx.x & 63;
    __shared__ int sh[2][64];
    int v = (t < SCAN_NB) ? g_bsum[sel][t] : 0;
    sh[sel][t] = v;
    __syncthreads();
    #pragma unroll
    for (int o = 1; o < 64; o <<= 1) {
        int u = (t >= o) ? sh[sel][t - o] : 0;
        __syncthreads();
        sh[sel][t] += u;
        __syncthreads();
    }
    if (t < SCAN_NB) g_bsum[sel][t] = sh[sel][t] - v;   // exclusive
}

__global__ void scan_apply_all() {
    int sel = (blockIdx.x >= SCAN_NB) ? 1 : 0;
    int b = blockIdx.x - sel * SCAN_NB;
    const int n = sel ? N_NODES : N_EDGES;
    int i = b * 1024 + threadIdx.x;
    int lane = threadIdx.x & 31, w = threadIdx.x >> 5;
    int v = 0;
    if (i < n) v = sel ? g_ncnt[i] : g_ecnt[i];
    int s = v;
    #pragma unroll
    for (int o = 1; o < 32; o <<= 1) {
        int t = __shfl_up_sync(~0u, s, o);
        if (lane >= o) s += t;
    }
    __shared__ int wsum[32], wexc[32];
    if (lane == 31) wsum[w] = s;
    __syncthreads();
    if (w == 0) {
        int t = wsum[lane];
        int q = t;
        #pragma unroll
        for (int o = 1; o < 32; o <<= 1) {
            int u = __shfl_up_sync(~0u, q, o);
            if (lane >= o) q += u;
        }
        wexc[lane] = q - t;
    }
    __syncthreads();
    int excl = s - v + wexc[w] + g_bsum[sel][b];
    if (i < n) {
        if (sel) g_noff[i] = excl; else g_eoff[i] = excl;
        if (i == n - 1) { if (sel) g_noff[n] = excl + v; else g_eoff[n] = excl + v; }
    }
}

__global__ void perm_kernel(const void* __restrict__ he) {
    int i = blockIdx.x * blockDim.x + threadIdx.x;
    if (i >= NNZ) return;
    int n = idx_node(he, i);
    int e = idx_edge(he, i);
    if ((unsigned)n >= N_NODES || (unsigned)e >= N_EDGES) return;
    int pe = g_eoff[e] + atomicAdd(&g_ecur[e], 1);
    g_eadj[pe] = n;
    int pn = g_noff[n] + atomicAdd(&g_ncur[n], 1);
    g_nadj[pn] = e;
}

// ---------------- fused: GEMM1 (blocks < G1_BLOCKS) + histogram (rest) ----------
// GEMM1: g_xwh = fp16(X @ W1), M=N_NODES, K=256, N=128, FFMA2, BM=128, BK=16.
#define G1_BLOCKS ((N_NODES + 127) / 128)       // 391
#define HIST_BLOCKS ((NNZ + 255) / 256)         // 3125

__global__ void __launch_bounds__(256)
hist_gemm1_kernel(const void* __restrict__ he,
                  const float* __restrict__ X, const float* __restrict__ W1) {
    if (blockIdx.x >= G1_BLOCKS) {
        int i = (blockIdx.x - G1_BLOCKS) * 256 + threadIdx.x;
        if (i < NNZ) {
            int n = idx_node(he, i);
            int e = idx_edge(he, i);
            if ((unsigned)n < N_NODES) atomicAdd(&g_ncnt[n], 1);
            if ((unsigned)e < N_EDGES) atomicAdd(&g_ecnt[e], 1);
        }
        return;
    }

    constexpr int K = IN_C, N = HID_C, BM = 128, BK = 16, TN = N / 16;
    __shared__ float As[BK][BM + 4];
    __shared__ ull   BsD[BK][N];

    const int tid = threadIdx.x;
    const int tx = tid & 15;
    const int ty = tid >> 4;
    const int blockRow = blockIdx.x * BM;

    ull acc2[4][TN];
    #pragma unroll
    for (int p = 0; p < 4; p++)
        #pragma unroll
        for (int j = 0; j < TN; j++) acc2[p][j] = 0ull;

    for (int k0 = 0; k0 < K; k0 += BK) {
        #pragma unroll
        for (int l = 0; l < 2; l++) {
            int idx = tid + l * 256;
            int r = idx >> 2;
            int c4 = (idx & 3) * 4;
            int grow = blockRow + r;
            float4 v = make_float4(0.f, 0.f, 0.f, 0.f);
            if (grow < N_NODES)
                v = *reinterpret_cast<const float4*>(X + (size_t)grow * K + k0 + c4);
            As[c4 + 0][r] = v.x; As[c4 + 1][r] = v.y;
            As[c4 + 2][r] = v.z; As[c4 + 3][r] = v.w;
        }
        #pragma unroll
        for (int l = 0; l < BK / 8; l++) {
            int r = l * 8 + (tid >> 5);
            int c0 = tid & 31;
            #pragma unroll
            for (int q = 0; q < N / 32; q++) {
                float v = W1[(size_t)(k0 + r) * N + c0 + 32 * q];
                BsD[r][c0 + 32 * q] = dup2(v);
            }
        }
        __syncthreads();

        #pragma unroll
        for (int k = 0; k < BK; k++) {
            ulonglong2 aA = *reinterpret_cast<const ulonglong2*>(&As[k][ty * 8]);
            ulonglong2 aB = *reinterpret_cast<const ulonglong2*>(&As[k][ty * 8 + 4]);
            ull ap[4] = { aA.x, aA.y, aB.x, aB.y };
            ull bp[TN];
            #pragma unroll
            for (int j = 0; j < TN; j++) bp[j] = BsD[k][tx + 16 * j];
            #pragma unroll
            for (int p = 0; p < 4; p++)
                #pragma unroll
                for (int j = 0; j < TN; j++)
                    fma2(acc2[p][j], ap[p], bp[j]);
        }
        __syncthreads();
    }

    #pragma unroll
    for (int p = 0; p < 4; p++) {
        int r0 = blockRow + ty * 8 + 2 * p;
        int r1 = r0 + 1;
        float lo[TN], hi[TN];
        #pragma unroll
        for (int j = 0; j < TN; j++) unpack2(acc2[p][j], lo[j], hi[j]);
        if (r0 < N_NODES) {
            #pragma unroll
            for (int j = 0; j < TN; j++)
                g_xwh[(size_t)r0 * N + tx + 16 * j] = __half_as_ushort(__float2half_rn(lo[j]));
        }
        if (r1 < N_NODES) {
            #pragma unroll
            for (int j = 0; j < TN; j++)
                g_xwh[(size_t)r1 * N + tx + 16 * j] = __half_as_ushort(__float2half_rn(hi[j]));
        }
    }
}

// ---------------- warp-per-row fp16 gather, unroll x4 ----------------
// SRC_SEL: 0 = g_xwh, 1 = g_mh.  DST_SEL: 0 = g_mh (fp16), 1 = fp32 param.
template<int F, bool RELU, int SRC_SEL, int DST_SEL>
__global__ void gather_rows_h(const int* __restrict__ adj,
                              const int* __restrict__ off,
                              const float* __restrict__ bias,
                              float* __restrict__ dst_param, int nrows) {
    constexpr int VEC = F / 32;           // 4 (F=128) or 2 (F=64) halves per lane
    int warp = (blockIdx.x * blockDim.x + threadIdx.x) >> 5;
    int lane = threadIdx.x & 31;
    if (warp >= nrows) return;

    const ushort* src = (SRC_SEL == 0) ? g_xwh : g_mh;

    int s = off[warp];
    int e = off[warp + 1];

    float acc[VEC];
    #pragma unroll
    for (int k = 0; k < VEC; k++) acc[k] = 0.0f;

    int j = s;
    for (; j + 3 < e; j += 4) {
        int r0 = adj[j], r1 = adj[j+1], r2 = adj[j+2], r3 = adj[j+3];
        if (VEC == 4) {
            uint2 u0 = *reinterpret_cast<const uint2*>(src + (size_t)r0 * F + lane * 4);
            uint2 u1 = *reinterpret_cast<const uint2*>(src + (size_t)r1 * F + lane * 4);
            uint2 u2 = *reinterpret_cast<const uint2*>(src + (size_t)r2 * F + lane * 4);
            uint2 u3 = *reinterpret_cast<const uint2*>(src + (size_t)r3 * F + lane * 4);
            float2 a0 = __half22float2(*(const __half2*)&u0.x), b0 = __half22float2(*(const __half2*)&u0.y);
            float2 a1 = __half22float2(*(const __half2*)&u1.x), b1 = __half22float2(*(const __half2*)&u1.y);
            float2 a2 = __half22float2(*(const __half2*)&u2.x), b2 = __half22float2(*(const __half2*)&u2.y);
            float2 a3 = __half22float2(*(const __half2*)&u3.x), b3 = __half22float2(*(const __half2*)&u3.y);
            acc[0] += (a0.x + a1.x) + (a2.x + a3.x);
            acc[1] += (a0.y + a1.y) + (a2.y + a3.y);
            acc[VEC>2?2:0] += (b0.x + b1.x) + (b2.x + b3.x);
            acc[VEC>3?3:0] += (b0.y + b1.y) + (b2.y + b3.y);
        } else {
            unsigned u0 = *reinterpret_cast<const unsigned*>(src + (size_t)r0 * F + lane * 2);
            unsigned u1 = *reinterpret_cast<const unsigned*>(src + (size_t)r1 * F + lane * 2);
            unsigned u2 = *reinterpret_cast<const unsigned*>(src + (size_t)r2 * F + lane * 2);
            unsigned u3 = *reinterpret_cast<const unsigned*>(src + (size_t)r3 * F + lane * 2);
            float2 a0 = __half22float2(*(const __half2*)&u0);
            float2 a1 = __half22float2(*(const __half2*)&u1);
            float2 a2 = __half22float2(*(const __half2*)&u2);
            float2 a3 = __half22float2(*(const __half2*)&u3);
            acc[0] += (a0.x + a1.x) + (a2.x + a3.x);
            acc[1] += (a0.y + a1.y) + (a2.y + a3.y);
        }
    }
    for (; j < e; j++) {
        int r = adj[j];
        if (VEC == 4) {
            uint2 u = *reinterpret_cast<const uint2*>(src + (size_t)r * F + lane * 4);
            float2 a = __half22float2(*(const __half2*)&u.x), b = __half22float2(*(const __half2*)&u.y);
            acc[0] += a.x; acc[1] += a.y;
            acc[VEC>2?2:0] += b.x; acc[VEC>3?3:0] += b.y;
        } else {
            unsigned u = *reinterpret_cast<const unsigned*>(src + (size_t)r * F + lane * 2);
            float2 a = __half22float2(*(const __half2*)&u);
            acc[0] += a.x; acc[1] += a.y;
        }
    }

    float inv = (e > s) ? (1.0f / (float)(e - s)) : 0.0f;

    if (DST_SEL == 0) {
        // fp16 store into g_mh
        if (VEC == 4) {
            __half2 h0 = __floats2half2_rn(acc[0] * inv, acc[1] * inv);
            __half2 h1 = __floats2half2_rn(acc[VEC>2?2:0] * inv, acc[VEC>3?3:0] * inv);
            uint2 o; o.x = *(const unsigned*)&h0; o.y = *(const unsigned*)&h1;
            *reinterpret_cast<uint2*>(g_mh + (size_t)warp * F + lane * 4) = o;
        } else {
            __half2 h0 = __floats2half2_rn(acc[0] * inv, acc[1] * inv);
            *reinterpret_cast<unsigned*>(g_mh + (size_t)warp * F + lane * 2) = *(const unsigned*)&h0;
        }
    } else {
        float* d = dst_param + (size_t)warp * F + lane * VEC;
        if (VEC == 4) {
            float4 o;
            if (RELU) {
                o.x = fmaxf(fmaf(acc[0], inv, bias[lane*4+0]), 0.f);
                o.y = fmaxf(fmaf(acc[1], inv, bias[lane*4+1]), 0.f);
                o.z = fmaxf(fmaf(acc[VEC>2?2:0], inv, bias[lane*4+2]), 0.f);
                o.w = fmaxf(fmaf(acc[VEC>3?3:0], inv, bias[lane*4+3]), 0.f);
            } else {
                o.x = acc[0]*inv; o.y = acc[1]*inv;
                o.z = acc[VEC>2?2:0]*inv; o.w = acc[VEC>3?3:0]*inv;
            }
            *reinterpret_cast<float4*>(d) = o;
        } else {
            float2 o;
            if (RELU) {
                o.x = fmaxf(fmaf(acc[0], inv, bias[lane*2+0]), 0.f);
                o.y = fmaxf(fmaf(acc[1], inv, bias[lane*2+1]), 0.f);
            } else {
                o.x = acc[0]*inv; o.y = acc[1]*inv;
            }
            *reinterpret_cast<float2*>(d) = o;
        }
    }
}

// ---------------- FFMA2 SGEMM (layers 2/3): C = A @ B (+bias) ----------------
// OUT_HALF: write fp16 into g_xwh; else fp32 into C param.
template<int K, int N, bool OUT_HALF>
__global__ void __launch_bounds__(256)
gemm_kernel(const float* __restrict__ A, const float* __restrict__ B,
            const float* __restrict__ bias, float* __restrict__ C, int M) {
    constexpr int BM = 128, BK = 16;
    constexpr int TN = N / 16;
    __shared__ float As[BK][BM + 4];
    __shared__ ull   BsD[BK][N];

    const int tid = threadIdx.x;
    const int tx = tid & 15;
    const int ty = tid >> 4;
    const int blockRow = blockIdx.x * BM;

    ull acc2[4][TN];
    #pragma unroll
    for (int p = 0; p < 4; p++)
        #pragma unroll
        for (int j = 0; j < TN; j++) acc2[p][j] = 0ull;

    for (int k0 = 0; k0 < K; k0 += BK) {
        #pragma unroll
        for (int l = 0; l < 2; l++) {
            int idx = tid + l * 256;
            int r = idx >> 2;
            int c4 = (idx & 3) * 4;
            int grow = blockRow + r;
            float4 v = make_float4(0.f, 0.f, 0.f, 0.f);
            if (grow < M)
                v = *reinterpret_cast<const float4*>(A + (size_t)grow * K + k0 + c4);
            As[c4 + 0][r] = v.x; As[c4 + 1][r] = v.y;
            As[c4 + 2][r] = v.z; As[c4 + 3][r] = v.w;
        }
        #pragma unroll
        for (int l = 0; l < BK / 8; l++) {
            int r = l * 8 + (tid >> 5);
            int c0 = tid & 31;
            #pragma unroll
            for (int q = 0; q < N / 32; q++) {
                float v = B[(size_t)(k0 + r) * N + c0 + 32 * q];
                BsD[r][c0 + 32 * q] = dup2(v);
            }
        }
        __syncthreads();

        #pragma unroll
        for (int k = 0; k < BK; k++) {
            ulonglong2 aA = *reinterpret_cast<const ulonglong2*>(&As[k][ty * 8]);
            ulonglong2 aB = *reinterpret_cast<const ulonglong2*>(&As[k][ty * 8 + 4]);
            ull ap[4] = { aA.x, aA.y, aB.x, aB.y };
            ull bp[TN];
            #pragma unroll
            for (int j = 0; j < TN; j++) bp[j] = BsD[k][tx + 16 * j];
            #pragma unroll
            for (int p = 0; p < 4; p++)
                #pragma unroll
                for (int j = 0; j < TN; j++)
                    fma2(acc2[p][j], ap[p], bp[j]);
        }
        __syncthreads();
    }

    #pragma unroll
    for (int p = 0; p < 4; p++) {
        int r0 = blockRow + ty * 8 + 2 * p;
        int r1 = r0 + 1;
        float lo[TN], hi[TN];
        #pragma unroll
        for (int j = 0; j < TN; j++) unpack2(acc2[p][j], lo[j], hi[j]);
        if (bias) {
            #pragma unroll
            for (int j = 0; j < TN; j++) {
                float b = bias[tx + 16 * j];
                lo[j] += b; hi[j] += b;
            }
        }
        if (OUT_HALF) {
            if (r0 < M) {
                #pragma unroll
                for (int j = 0; j < TN; j++)
                    g_xwh[(size_t)r0 * N + tx + 16 * j] = __half_as_ushort(__float2half_rn(lo[j]));
            }
            if (r1 < M) {
                #pragma unroll
                for (int j = 0; j < TN; j++)
                    g_xwh[(size_t)r1 * N + tx + 16 * j] = __half_as_ushort(__float2half_rn(hi[j]));
            }
        } else {
            if (r0 < M) {
                #pragma unroll
                for (int j = 0; j < TN; j++) C[(size_t)r0 * N + tx + 16 * j] = lo[j];
            }
            if (r1 < M) {
                #pragma unroll
                for (int j = 0; j < TN; j++) C[(size_t)r1 * N + tx + 16 * j] = hi[j];
            }
        }
    }
}

// ---------------- launch ----------------
extern "C" void kernel_launch(void* const* d_in, const int* in_sizes, int n_in,
                              void* d_out, int out_size) {
    const float* x  = (const float*)d_in[0];
    const void*  he = d_in[1];
    const float* W1 = (const float*)d_in[2];
    const float* b1 = (const float*)d_in[3];
    const float* W2 = (const float*)d_in[4];
    const float* b2 = (const float*)d_in[5];
    const float* Wp = (const float*)d_in[6];
    const float* bp = (const float*)d_in[7];

    float* out  = (float*)d_out;
    float* zout = out;                                  // [N, 64]
    float* f1   = out + (size_t)N_NODES * OUT_C;        // [N, 128]
    float* f2   = f1  + (size_t)N_NODES * HID_C;        // [N, 64]

    const int T = 256;
    auto blocks = [](long long n, int t) { return (int)((n + t - 1) / t); };
    const int gemm_grid = (N_NODES + 127) / 128;        // 391
    const int gather_grid = (N_NODES * 32 + T - 1) / T;

    int *p_eoff, *p_noff, *p_eadj, *p_nadj;
    cudaGetSymbolAddress((void**)&p_eoff, g_eoff);
    cudaGetSymbolAddress((void**)&p_noff, g_noff);
    cudaGetSymbolAddress((void**)&p_eadj, g_eadj);
    cudaGetSymbolAddress((void**)&p_nadj, g_nadj);

    // CSR prep + dtype flag
    zero_counts_kernel<<<blocks(N_EDGES, T), T>>>();
    detect_dtype_kernel<<<8, 256>>>(he);

    // fused: GEMM1 (X@W1 -> g_xwh fp16) + histogram
    hist_gemm1_kernel<<<G1_BLOCKS + HIST_BLOCKS, 256>>>(he, x, W1);

    // CSR finish
    scan_reduce_all<<<2 * SCAN_NB, 1024>>>();
    scan_partials<<<1, 128>>>();
    scan_apply_all<<<2 * SCAN_NB, 1024>>>();
    perm_kernel<<<blocks(NNZ, T), T>>>(he);

    // ---- layer 1: F = 128 ----
    gather_rows_h<HID_C, false, 0, 0><<<gather_grid, T>>>(p_eadj, p_eoff, nullptr, nullptr, N_EDGES);
    gather_rows_h<HID_C, true, 1, 1><<<gather_grid, T>>>(p_nadj, p_noff, b1, f1, N_NODES);

    // ---- layer 2: F = 64 ----
    gemm_kernel<HID_C, OUT_C, true><<<gemm_grid, 256>>>(f1, W2, nullptr, nullptr, N_NODES);
    gather_rows_h<OUT_C, false, 0, 0><<<gather_grid, T>>>(p_eadj, p_eoff, nullptr, nullptr, N_EDGES);
    gather_rows_h<OUT_C, true, 1, 1><<<gather_grid, T>>>(p_nadj, p_noff, b2, f2, N_NODES);

    // ---- projection head: z = f2 @ Wp + bp ----
    gemm_kernel<OUT_C, OUT_C, false><<<gemm_grid, 256>>>(f2, Wp, bp, zout, N_NODES);
}